// round 12
// baseline (speedup 1.0000x reference)
#include <cuda_runtime.h>
#include <cuda_bf16.h>
#include <math.h>

#define NN 100000
#define NE 1600000
#define DD 512
#define HH 256
#define KK 64
#define SCAN_B 256
#define SCAN_NB ((NN + SCAN_B - 1) / SCAN_B)   // 391

// Scratch: __device__ globals, referenced ONLY from device code.
__device__ float4   g_hw4[(size_t)NN * HH / 4];     // GEMM f32 output (message source)
// pre-split bf16 operands: packed k-pairs, u32 = (bf16 k_even | bf16 k_odd<<16)
__device__ unsigned g_xhi[(size_t)NN * DD / 2], g_xlo[(size_t)NN * DD / 2];
__device__ unsigned g_h1hi[(size_t)NN * HH / 2], g_h1lo[(size_t)NN * HH / 2];
__device__ unsigned g_h2hi[(size_t)NN * HH / 2], g_h2lo[(size_t)NN * HH / 2];
__device__ unsigned g_w1hi[(DD / 2) * HH], g_w1lo[(DD / 2) * HH];
__device__ unsigned g_w2hi[(HH / 2) * HH], g_w2lo[(HH / 2) * HH];
__device__ unsigned g_wkhi[(HH / 2) * KK], g_wklo[(HH / 2) * KK];
__device__ float    g_dinv[NN];
__device__ int      g_deg[NN];
__device__ int      g_off[NN + 1];
__device__ int      g_cur[NN];
__device__ int      g_csr[NE];
__device__ int      g_blocksum[SCAN_NB];
__device__ int      g_is64;

// ---------------------------------------------------------------------------
__device__ __forceinline__ void split2(float a, float b, unsigned& hi, unsigned& lo) {
    __nv_bfloat16 ha = __float2bfloat16(a);
    __nv_bfloat16 hb = __float2bfloat16(b);
    __nv_bfloat16 la = __float2bfloat16(a - __bfloat162float(ha));
    __nv_bfloat16 lb = __float2bfloat16(b - __bfloat162float(hb));
    hi = (unsigned)__bfloat16_as_ushort(ha) | ((unsigned)__bfloat16_as_ushort(hb) << 16);
    lo = (unsigned)__bfloat16_as_ushort(la) | ((unsigned)__bfloat16_as_ushort(lb) << 16);
}

// ---------------------------------------------------------------------------
// Edge dtype detection
// ---------------------------------------------------------------------------
__global__ void k_detect(const int* ei_raw) {
    if (threadIdx.x == 0 && blockIdx.x == 0) {
        int all0 = 1;
        for (int i = 0; i < 64; i++)
            if (ei_raw[2 * i + 1] != 0) { all0 = 0; break; }
        g_is64 = all0;
    }
}

__device__ __forceinline__ int edge_at(const int* ei_raw, size_t idx) {
    return g_is64 ? ei_raw[2 * idx] : ei_raw[idx];
}

// ---------------------------------------------------------------------------
// CSR build + norms
// ---------------------------------------------------------------------------
__global__ void k_zero() {
    int i = blockIdx.x * blockDim.x + threadIdx.x;
    if (i < NN) { g_deg[i] = 0; g_cur[i] = 0; }
}

__global__ void k_deg_count(const int* ei_raw) {
    int e = blockIdx.x * blockDim.x + threadIdx.x;
    if (e >= NE) return;
    int d = edge_at(ei_raw, (size_t)NE + e);
    if (d >= 0 && d < NN) atomicAdd(&g_deg[d], 1);
}

__global__ void k_dinv() {
    int i = blockIdx.x * blockDim.x + threadIdx.x;
    if (i < NN) g_dinv[i] = rsqrtf((float)(g_deg[i] + 1));
}

__global__ void k_scan_reduce() {
    __shared__ int sh[SCAN_B];
    int i = blockIdx.x * SCAN_B + threadIdx.x;
    sh[threadIdx.x] = (i < NN) ? g_deg[i] : 0;
    __syncthreads();
    for (int s = SCAN_B / 2; s > 0; s >>= 1) {
        if (threadIdx.x < s) sh[threadIdx.x] += sh[threadIdx.x + s];
        __syncthreads();
    }
    if (threadIdx.x == 0) g_blocksum[blockIdx.x] = sh[0];
}

__global__ void k_scan_bases() {
    __shared__ int sh[512];
    int i = threadIdx.x;
    int v = (i < SCAN_NB) ? g_blocksum[i] : 0;
    sh[i] = v;
    __syncthreads();
    for (int s = 1; s < 512; s <<= 1) {
        int t = (i >= s) ? sh[i - s] : 0;
        __syncthreads();
        sh[i] += t;
        __syncthreads();
    }
    if (i < SCAN_NB) g_blocksum[i] = sh[i] - v;
    if (i == SCAN_NB - 1) g_off[NN] = sh[i];
}

__global__ void k_scan_offsets() {
    __shared__ int sh[SCAN_B];
    int i = blockIdx.x * SCAN_B + threadIdx.x;
    int v = (i < NN) ? g_deg[i] : 0;
    sh[threadIdx.x] = v;
    __syncthreads();
    for (int s = 1; s < SCAN_B; s <<= 1) {
        int t = (threadIdx.x >= s) ? sh[threadIdx.x - s] : 0;
        __syncthreads();
        sh[threadIdx.x] += t;
        __syncthreads();
    }
    if (i < NN) g_off[i] = g_blocksum[blockIdx.x] + sh[threadIdx.x] - v;
}

__global__ void k_fill(const int* ei_raw) {
    int e = blockIdx.x * blockDim.x + threadIdx.x;
    if (e >= NE) return;
    int s = edge_at(ei_raw, (size_t)e);
    int d = edge_at(ei_raw, (size_t)NE + e);
    if ((unsigned)s >= NN || (unsigned)d >= NN) return;
    int pos = g_off[d] + atomicAdd(&g_cur[d], 1);
    g_csr[pos] = s;
}

// ---------------------------------------------------------------------------
// Pre-split kernels
// ---------------------------------------------------------------------------
__global__ void k_presplit_x(const float* x) {
    int idx = blockIdx.x * blockDim.x + threadIdx.x;        // [m][k2] linear
    const int TOT = NN * (DD / 2);
    if (idx >= TOT) return;
    float2 v = ((const float2*)x)[idx];
    split2(v.x, v.y, g_xhi[idx], g_xlo[idx]);
}

// SEL: 1=W1(Kc2=256,Nc=256) 2=W2(128,256) 3=Wk(128,64)
template<int SEL>
__global__ void k_presplit_W(const float* B, int Kc2, int Nc) {
    int idx = blockIdx.x * blockDim.x + threadIdx.x;
    if (idx >= Kc2 * Nc) return;
    int k2 = idx / Nc, n = idx - k2 * Nc;
    float a = B[(size_t)(2 * k2    ) * Nc + n];
    float b = B[(size_t)(2 * k2 + 1) * Nc + n];
    unsigned* Whi = (SEL == 1) ? g_w1hi : (SEL == 2) ? g_w2hi : g_wkhi;
    unsigned* Wlo = (SEL == 1) ? g_w1lo : (SEL == 2) ? g_w2lo : g_wklo;
    split2(a, b, Whi[idx], Wlo[idx]);
}

// ---------------------------------------------------------------------------
// Split-bf16 tensor GEMM on pre-split operands (no conversions in-loop).
// C[M,Nc] = A @ B; acc += lo*hi' + hi*lo' + hi*hi' (fp32 accum).
// BM=128, BN=64, BK=16, 256 thr (8 warps 4m x 2n), warp tile 32x32.
// A_SEL: 0=x 1=h1 2=h2.  B_SEL: 1=W1 2=W2 3=Wk.  C_DST: 0=ext 1=g_hw.
// ---------------------------------------------------------------------------
template<int A_SEL, int B_SEL, int C_DST>
__global__ void k_mma_gemm(float* Cext, int M, int Kc, int Nc) {
    const unsigned* Ahi = (A_SEL == 0) ? g_xhi : (A_SEL == 1) ? g_h1hi : g_h2hi;
    const unsigned* Alo = (A_SEL == 0) ? g_xlo : (A_SEL == 1) ? g_h1lo : g_h2lo;
    const unsigned* Bhi = (B_SEL == 1) ? g_w1hi : (B_SEL == 2) ? g_w2hi : g_wkhi;
    const unsigned* Blo = (B_SEL == 1) ? g_w1lo : (B_SEL == 2) ? g_w2lo : g_wklo;
    float* C = (C_DST == 1) ? (float*)g_hw4 : Cext;

    const int BM = 128, BN = 64;
    const int Kc2 = Kc >> 1;
    __shared__ unsigned AsH[BM][9], AsL[BM][9];
    __shared__ unsigned BsH[8][BN + 1], BsL[8][BN + 1];

    int tid  = threadIdx.x;
    int wid  = tid >> 5;
    int lane = tid & 31;
    int wm   = wid >> 1;
    int wn   = wid & 1;
    int brow = blockIdx.y * BM;
    int bcol = blockIdx.x * BN;

    float acc[2][4][4];
    #pragma unroll
    for (int i = 0; i < 2; i++)
        #pragma unroll
        for (int j = 0; j < 4; j++)
            #pragma unroll
            for (int r = 0; r < 4; r++) acc[i][j][r] = 0.0f;

    int ar   = tid >> 1;          // A row 0..127
    int apo  = (tid & 1) << 2;    // 0 or 4 (k2 quad)
    int br2  = tid >> 5;          // B k2 row 0..7
    int bnc  = (tid & 31) << 1;   // B col 0..62

    for (int k20 = 0; k20 < Kc2; k20 += 8) {
        {
            int gr = brow + ar;
            uint4 h = make_uint4(0, 0, 0, 0), l = make_uint4(0, 0, 0, 0);
            if (gr < M) {
                size_t base = (size_t)gr * Kc2 + k20 + apo;
                h = *(const uint4*)(Ahi + base);
                l = *(const uint4*)(Alo + base);
            }
            AsH[ar][apo + 0] = h.x; AsH[ar][apo + 1] = h.y;
            AsH[ar][apo + 2] = h.z; AsH[ar][apo + 3] = h.w;
            AsL[ar][apo + 0] = l.x; AsL[ar][apo + 1] = l.y;
            AsL[ar][apo + 2] = l.z; AsL[ar][apo + 3] = l.w;
        }
        {
            size_t base = (size_t)(k20 + br2) * Nc + bcol + bnc;
            uint2 h = *(const uint2*)(Bhi + base);
            uint2 l = *(const uint2*)(Blo + base);
            BsH[br2][bnc] = h.x; BsH[br2][bnc + 1] = h.y;
            BsL[br2][bnc] = l.x; BsL[br2][bnc + 1] = l.y;
        }
        __syncthreads();

        {
            int t = lane & 3;
            int g = lane >> 2;
            unsigned ah[2][4], al[2][4];
            #pragma unroll
            for (int fm = 0; fm < 2; fm++) {
                int r0 = wm * 32 + fm * 16 + g;
                ah[fm][0] = AsH[r0    ][t    ];
                ah[fm][1] = AsH[r0 + 8][t    ];
                ah[fm][2] = AsH[r0    ][t + 4];
                ah[fm][3] = AsH[r0 + 8][t + 4];
                al[fm][0] = AsL[r0    ][t    ];
                al[fm][1] = AsL[r0 + 8][t    ];
                al[fm][2] = AsL[r0    ][t + 4];
                al[fm][3] = AsL[r0 + 8][t + 4];
            }
            unsigned bh[4][2], bl[4][2];
            #pragma unroll
            for (int fn = 0; fn < 4; fn++) {
                int cc = wn * 32 + fn * 8 + g;
                bh[fn][0] = BsH[t    ][cc];
                bh[fn][1] = BsH[t + 4][cc];
                bl[fn][0] = BsL[t    ][cc];
                bl[fn][1] = BsL[t + 4][cc];
            }
            #pragma unroll
            for (int fm = 0; fm < 2; fm++)
                #pragma unroll
                for (int fn = 0; fn < 4; fn++) {
                    float* d = acc[fm][fn];
                    asm volatile(
                        "mma.sync.aligned.m16n8k16.row.col.f32.bf16.bf16.f32 "
                        "{%0,%1,%2,%3}, {%4,%5,%6,%7}, {%8,%9}, {%0,%1,%2,%3};"
                        : "+f"(d[0]), "+f"(d[1]), "+f"(d[2]), "+f"(d[3])
                        : "r"(al[fm][0]), "r"(al[fm][1]), "r"(al[fm][2]), "r"(al[fm][3]),
                          "r"(bh[fn][0]), "r"(bh[fn][1]));
                    asm volatile(
                        "mma.sync.aligned.m16n8k16.row.col.f32.bf16.bf16.f32 "
                        "{%0,%1,%2,%3}, {%4,%5,%6,%7}, {%8,%9}, {%0,%1,%2,%3};"
                        : "+f"(d[0]), "+f"(d[1]), "+f"(d[2]), "+f"(d[3])
                        : "r"(ah[fm][0]), "r"(ah[fm][1]), "r"(ah[fm][2]), "r"(ah[fm][3]),
                          "r"(bl[fn][0]), "r"(bl[fn][1]));
                    asm volatile(
                        "mma.sync.aligned.m16n8k16.row.col.f32.bf16.bf16.f32 "
                        "{%0,%1,%2,%3}, {%4,%5,%6,%7}, {%8,%9}, {%0,%1,%2,%3};"
                        : "+f"(d[0]), "+f"(d[1]), "+f"(d[2]), "+f"(d[3])
                        : "r"(ah[fm][0]), "r"(ah[fm][1]), "r"(ah[fm][2]), "r"(ah[fm][3]),
                          "r"(bh[fn][0]), "r"(bh[fn][1]));
                }
        }
        __syncthreads();
    }

    #pragma unroll
    for (int fm = 0; fm < 2; fm++) {
        int row0 = brow + wm * 32 + fm * 16 + (lane >> 2);
        #pragma unroll
        for (int half = 0; half < 2; half++) {
            int row = row0 + half * 8;
            if (row >= M) continue;
            #pragma unroll
            for (int fn = 0; fn < 4; fn++) {
                int col = bcol + wn * 32 + fn * 8 + 2 * (lane & 3);
                *(float2*)(C + (size_t)row * Nc + col) =
                    make_float2(acc[fm][fn][half * 2 + 0], acc[fm][fn][half * 2 + 1]);
            }
        }
    }
}

// ---------------------------------------------------------------------------
// CSR gather aggregation: warp per node, no atomics. Emits PRE-SPLIT output.
// h[node] = bias + dinv^2 * hw[node] + sum_in (dinv[n]*dinv[s]) * hw[s]
// DST: 1 -> g_h1 (with RELU), 2 -> g_h2 (no relu)
// ---------------------------------------------------------------------------
template<int DST, bool RELU>
__global__ void k_agg_gather(const float* bias) {
    int gtid = blockIdx.x * blockDim.x + threadIdx.x;
    int node = gtid >> 5;
    int lane = gtid & 31;
    if (node >= NN) return;

    float di = g_dinv[node];
    float ws = di * di;
    const float4* hw = g_hw4 + (size_t)node * (HH / 4);
    float4 b0 = ((const float4*)bias)[lane];
    float4 b1 = ((const float4*)bias)[lane + 32];
    float4 v0 = hw[lane];
    float4 v1 = hw[lane + 32];
    float4 a0 = make_float4(fmaf(ws, v0.x, b0.x), fmaf(ws, v0.y, b0.y),
                            fmaf(ws, v0.z, b0.z), fmaf(ws, v0.w, b0.w));
    float4 a1 = make_float4(fmaf(ws, v1.x, b1.x), fmaf(ws, v1.y, b1.y),
                            fmaf(ws, v1.z, b1.z), fmaf(ws, v1.w, b1.w));

    int e0 = g_off[node], e1 = g_off[node + 1];
    for (int i = e0; i < e1; i++) {
        int s = g_csr[i];
        float w = di * g_dinv[s];
        const float4* hs = g_hw4 + (size_t)s * (HH / 4);
        float4 u0 = hs[lane];
        float4 u1 = hs[lane + 32];
        a0.x = fmaf(w, u0.x, a0.x); a0.y = fmaf(w, u0.y, a0.y);
        a0.z = fmaf(w, u0.z, a0.z); a0.w = fmaf(w, u0.w, a0.w);
        a1.x = fmaf(w, u1.x, a1.x); a1.y = fmaf(w, u1.y, a1.y);
        a1.z = fmaf(w, u1.z, a1.z); a1.w = fmaf(w, u1.w, a1.w);
    }

    if (RELU) {
        a0.x = fmaxf(a0.x, 0.f); a0.y = fmaxf(a0.y, 0.f);
        a0.z = fmaxf(a0.z, 0.f); a0.w = fmaxf(a0.w, 0.f);
        a1.x = fmaxf(a1.x, 0.f); a1.y = fmaxf(a1.y, 0.f);
        a1.z = fmaxf(a1.z, 0.f); a1.w = fmaxf(a1.w, 0.f);
    }

    unsigned* Hhi = (DST == 1) ? g_h1hi : g_h2hi;
    unsigned* Hlo = (DST == 1) ? g_h1lo : g_h2lo;
    size_t rb = (size_t)node * (HH / 2);
    unsigned h0, l0, h1, l1;
    split2(a0.x, a0.y, h0, l0);
    split2(a0.z, a0.w, h1, l1);
    *(uint2*)(Hhi + rb + 2 * lane) = make_uint2(h0, h1);
    *(uint2*)(Hlo + rb + 2 * lane) = make_uint2(l0, l1);
    split2(a1.x, a1.y, h0, l0);
    split2(a1.z, a1.w, h1, l1);
    *(uint2*)(Hhi + rb + 64 + 2 * lane) = make_uint2(h0, h1);
    *(uint2*)(Hlo + rb + 64 + 2 * lane) = make_uint2(l0, l1);
}

// ---------------------------------------------------------------------------
// Softmax over K=64, warp per row. d_out layout: [S | logits], each NN*KK.
// ---------------------------------------------------------------------------
__global__ void k_softmax(const float* log_tau, float* out) {
    int gtid = blockIdx.x * blockDim.x + threadIdx.x;
    int row  = gtid >> 5;
    int lane = gtid & 31;
    if (row >= NN) return;
    const float* lg = out + (size_t)NN * KK + (size_t)row * KK;
    float inv_tau = __expf(-log_tau[0]);
    float a = lg[lane] * inv_tau;
    float b = lg[lane + 32] * inv_tau;
    float m = fmaxf(a, b);
    #pragma unroll
    for (int off = 16; off > 0; off >>= 1)
        m = fmaxf(m, __shfl_xor_sync(0xFFFFFFFFu, m, off));
    float e0 = __expf(a - m);
    float e1 = __expf(b - m);
    float s = e0 + e1;
    #pragma unroll
    for (int off = 16; off > 0; off >>= 1)
        s += __shfl_xor_sync(0xFFFFFFFFu, s, off);
    float inv = 1.0f / s;
    float* S = out + (size_t)row * KK;
    S[lane]      = e0 * inv;
    S[lane + 32] = e1 * inv;
}

// ---------------------------------------------------------------------------
extern "C" void kernel_launch(void* const* d_in, const int* in_sizes, int n_in,
                              void* d_out, int out_size) {
    const float* x       = (const float*)d_in[0];
    const int*   ei_raw  = (const int*)d_in[1];
    const float* W1      = (const float*)d_in[2];
    const float* b1      = (const float*)d_in[3];
    const float* W2      = (const float*)d_in[4];
    const float* b2      = (const float*)d_in[5];
    const float* Wk      = (const float*)d_in[6];
    const float* log_tau = (const float*)d_in[7];
    float* out = (float*)d_out;

    // CSR build + norms
    k_detect      <<<1, 32>>>(ei_raw);
    k_zero        <<<(NN + 255) / 256, 256>>>();
    k_deg_count   <<<(NE + 255) / 256, 256>>>(ei_raw);
    k_dinv        <<<(NN + 255) / 256, 256>>>();
    k_scan_reduce <<<SCAN_NB, SCAN_B>>>();
    k_scan_bases  <<<1, 512>>>();
    k_scan_offsets<<<SCAN_NB, SCAN_B>>>();
    k_fill        <<<(NE + 255) / 256, 256>>>(ei_raw);

    // Pre-split inputs + weights
    k_presplit_x    <<<(NN * (DD / 2) + 255) / 256, 256>>>(x);
    k_presplit_W<1> <<<((DD / 2) * HH + 255) / 256, 256>>>(W1, DD / 2, HH);
    k_presplit_W<2> <<<((HH / 2) * HH + 255) / 256, 256>>>(W2, HH / 2, HH);
    k_presplit_W<3> <<<((HH / 2) * KK + 255) / 256, 256>>>(Wk, HH / 2, KK);

    dim3 grid_H(HH / 64, (NN + 127) / 128);
    dim3 grid_K(KK / 64, (NN + 127) / 128);
    int agg_blocks = (NN * 32 + 255) / 256;

    // Layer 1: hw = x @ W1 ; h1 = relu(agg) (pre-split on write)
    k_mma_gemm<0, 1, 1><<<grid_H, 256>>>(nullptr, NN, DD, HH);
    k_agg_gather<1, true><<<agg_blocks, 256>>>(b1);

    // Layer 2: hw = h1 @ W2 ; h2 = agg (pre-split on write)
    k_mma_gemm<1, 2, 1><<<grid_H, 256>>>(nullptr, NN, HH, HH);
    k_agg_gather<2, false><<<agg_blocks, 256>>>(b2);

    // Head: logits = h2 @ Wk ; softmax
    float* logits = out + (size_t)NN * KK;
    k_mma_gemm<2, 3, 0><<<grid_K, 256>>>(logits, NN, HH, KK);
    k_softmax<<<(NN + 7) / 8, 256>>>(log_tau, out);
}

// round 14
// speedup vs baseline: 1.1714x; 1.1714x over previous
#include <cuda_runtime.h>
#include <cuda_bf16.h>
#include <math.h>

#define NN 100000
#define NE 1600000
#define DD 512
#define HH 256
#define KK 64
#define SCAN_B 256
#define SCAN_NB ((NN + SCAN_B - 1) / SCAN_B)   // 391

// Scratch: __device__ globals, referenced ONLY from device code.
__device__ float4 g_hw4[(size_t)NN * HH / 4];   // GEMM output (message source)
__device__ float4 g_h4 [(size_t)NN * HH / 4];   // hidden state (layer 1)
__device__ float4 g_h24[(size_t)NN * HH / 4];   // hidden state (layer 2)
__device__ float  g_dinv[NN];                   // rsqrt(deg)
__device__ int    g_deg[NN];
__device__ int    g_off[NN + 1];
__device__ int    g_cur[NN];
__device__ int    g_csr[NE];
__device__ int    g_blocksum[SCAN_NB];
__device__ int    g_is64;

// ---------------------------------------------------------------------------
// Edge dtype detection
// ---------------------------------------------------------------------------
__global__ void k_detect(const int* ei_raw) {
    if (threadIdx.x == 0 && blockIdx.x == 0) {
        int all0 = 1;
        for (int i = 0; i < 64; i++)
            if (ei_raw[2 * i + 1] != 0) { all0 = 0; break; }
        g_is64 = all0;
    }
}

__device__ __forceinline__ int edge_at(const int* ei_raw, size_t idx) {
    return g_is64 ? ei_raw[2 * idx] : ei_raw[idx];
}

// ---------------------------------------------------------------------------
// CSR build + norms
// ---------------------------------------------------------------------------
__global__ void k_zero() {
    int i = blockIdx.x * blockDim.x + threadIdx.x;
    if (i < NN) { g_deg[i] = 0; g_cur[i] = 0; }
}

__global__ void k_deg_count(const int* ei_raw) {
    int e = blockIdx.x * blockDim.x + threadIdx.x;
    if (e >= NE) return;
    int d = edge_at(ei_raw, (size_t)NE + e);
    if (d >= 0 && d < NN) atomicAdd(&g_deg[d], 1);
}

__global__ void k_dinv() {
    int i = blockIdx.x * blockDim.x + threadIdx.x;
    if (i < NN) g_dinv[i] = rsqrtf((float)(g_deg[i] + 1));
}

__global__ void k_scan_reduce() {
    __shared__ int sh[SCAN_B];
    int i = blockIdx.x * SCAN_B + threadIdx.x;
    sh[threadIdx.x] = (i < NN) ? g_deg[i] : 0;
    __syncthreads();
    for (int s = SCAN_B / 2; s > 0; s >>= 1) {
        if (threadIdx.x < s) sh[threadIdx.x] += sh[threadIdx.x + s];
        __syncthreads();
    }
    if (threadIdx.x == 0) g_blocksum[blockIdx.x] = sh[0];
}

// parallel exclusive scan of 391 block sums (one block, 512 threads)
__global__ void k_scan_bases() {
    __shared__ int sh[512];
    int i = threadIdx.x;
    int v = (i < SCAN_NB) ? g_blocksum[i] : 0;
    sh[i] = v;
    __syncthreads();
    for (int s = 1; s < 512; s <<= 1) {
        int t = (i >= s) ? sh[i - s] : 0;
        __syncthreads();
        sh[i] += t;
        __syncthreads();
    }
    if (i < SCAN_NB) g_blocksum[i] = sh[i] - v;
    if (i == SCAN_NB - 1) g_off[NN] = sh[i];
}

__global__ void k_scan_offsets() {
    __shared__ int sh[SCAN_B];
    int i = blockIdx.x * SCAN_B + threadIdx.x;
    int v = (i < NN) ? g_deg[i] : 0;
    sh[threadIdx.x] = v;
    __syncthreads();
    for (int s = 1; s < SCAN_B; s <<= 1) {
        int t = (threadIdx.x >= s) ? sh[threadIdx.x - s] : 0;
        __syncthreads();
        sh[threadIdx.x] += t;
        __syncthreads();
    }
    if (i < NN) g_off[i] = g_blocksum[blockIdx.x] + sh[threadIdx.x] - v;
}

__global__ void k_fill(const int* ei_raw) {
    int e = blockIdx.x * blockDim.x + threadIdx.x;
    if (e >= NE) return;
    int s = edge_at(ei_raw, (size_t)e);
    int d = edge_at(ei_raw, (size_t)NE + e);
    if ((unsigned)s >= NN || (unsigned)d >= NN) return;
    int pos = g_off[d] + atomicAdd(&g_cur[d], 1);
    g_csr[pos] = s;
}

// ---------------------------------------------------------------------------
// Split-bf16 tensor GEMM, BK=32 (2 syncs per 32-k instead of per 16-k).
// C = op(A) @ B; x = hi+lo bf16; acc += lo*hi' + hi*lo' + hi*hi' (fp32 regs).
// BM=128, BN=64, 256 thr (8 warps 4m x 2n), warp tile 32x32.
// A_SRC: 0 ext / 1 g_h / 2 g_h2.  C_DST: 0 ext / 1 g_hw.
// ---------------------------------------------------------------------------
__device__ __forceinline__ void split2(float a, float b, unsigned& hi, unsigned& lo) {
    __nv_bfloat16 ha = __float2bfloat16(a);
    __nv_bfloat16 hb = __float2bfloat16(b);
    __nv_bfloat16 la = __float2bfloat16(a - __bfloat162float(ha));
    __nv_bfloat16 lb = __float2bfloat16(b - __bfloat162float(hb));
    hi = (unsigned)__bfloat16_as_ushort(ha) | ((unsigned)__bfloat16_as_ushort(hb) << 16);
    lo = (unsigned)__bfloat16_as_ushort(la) | ((unsigned)__bfloat16_as_ushort(lb) << 16);
}

template<bool RELU_A, int A_SRC, int C_DST>
__global__ void k_mma_gemm(const float* Aext, const float* B, float* Cext,
                           int M, int Kc, int Nc) {
    const float* A = (A_SRC == 1) ? (const float*)g_h4
                   : (A_SRC == 2) ? (const float*)g_h24 : Aext;
    float*       C = (C_DST == 1) ? (float*)g_hw4       : Cext;

    const int BM = 128, BN = 64, BK = 32;
    // k-pairs packed in u32: As[row][k2] (k2 = 0..15), Bs[k2][col]
    __shared__ unsigned AsH[BM][BK / 2 + 1], AsL[BM][BK / 2 + 1];
    __shared__ unsigned BsH[BK / 2][BN + 1], BsL[BK / 2][BN + 1];

    int tid  = threadIdx.x;
    int wid  = tid >> 5;
    int lane = tid & 31;
    int wm   = wid >> 1;
    int wn   = wid & 1;
    int brow = blockIdx.y * BM;
    int bcol = blockIdx.x * BN;

    float acc[2][4][4];
    #pragma unroll
    for (int i = 0; i < 2; i++)
        #pragma unroll
        for (int j = 0; j < 4; j++)
            #pragma unroll
            for (int r = 0; r < 4; r++) acc[i][j][r] = 0.0f;

    for (int k0 = 0; k0 < Kc; k0 += BK) {
        // A tile: 128x32 floats = 1024 float4, 4 per thread
        #pragma unroll
        for (int l = 0; l < 4; l++) {
            int f  = tid + l * 256;
            int ar = f >> 3;              // 0..127
            int fq = f & 7;               // float4 slot within row
            int ak = fq << 2;             // 0..28
            int gr = brow + ar;
            float4 v = make_float4(0.f, 0.f, 0.f, 0.f);
            if (gr < M) v = *(const float4*)(A + (size_t)gr * Kc + k0 + ak);
            if (RELU_A) {
                v.x = fmaxf(v.x, 0.f); v.y = fmaxf(v.y, 0.f);
                v.z = fmaxf(v.z, 0.f); v.w = fmaxf(v.w, 0.f);
            }
            int k2 = fq << 1;             // 0..14
            split2(v.x, v.y, AsH[ar][k2    ], AsL[ar][k2    ]);
            split2(v.z, v.w, AsH[ar][k2 + 1], AsL[ar][k2 + 1]);
        }
        // B tile: 32x64 floats; each thread loads 2 rows x 4 cols (k-pairs)
        {
            int r2 = tid >> 4;            // 0..15
            int bc = (tid & 15) << 2;     // 0..60
            float4 v0 = *(const float4*)(B + (size_t)(k0 + 2 * r2    ) * Nc + bcol + bc);
            float4 v1 = *(const float4*)(B + (size_t)(k0 + 2 * r2 + 1) * Nc + bcol + bc);
            split2(v0.x, v1.x, BsH[r2][bc + 0], BsL[r2][bc + 0]);
            split2(v0.y, v1.y, BsH[r2][bc + 1], BsL[r2][bc + 1]);
            split2(v0.z, v1.z, BsH[r2][bc + 2], BsL[r2][bc + 2]);
            split2(v0.w, v1.w, BsH[r2][bc + 3], BsL[r2][bc + 3]);
        }
        __syncthreads();

        #pragma unroll
        for (int sub = 0; sub < 2; sub++) {
            int t = (sub << 3) + (lane & 3);   // k2 base within BK
            int g = lane >> 2;
            unsigned ah[2][4], al[2][4];
            #pragma unroll
            for (int fm = 0; fm < 2; fm++) {
                int r0 = wm * 32 + fm * 16 + g;
                ah[fm][0] = AsH[r0    ][t    ];
                ah[fm][1] = AsH[r0 + 8][t    ];
                ah[fm][2] = AsH[r0    ][t + 4];
                ah[fm][3] = AsH[r0 + 8][t + 4];
                al[fm][0] = AsL[r0    ][t    ];
                al[fm][1] = AsL[r0 + 8][t    ];
                al[fm][2] = AsL[r0    ][t + 4];
                al[fm][3] = AsL[r0 + 8][t + 4];
            }
            unsigned bh[4][2], bl[4][2];
            #pragma unroll
            for (int fn = 0; fn < 4; fn++) {
                int cc = wn * 32 + fn * 8 + g;
                bh[fn][0] = BsH[t    ][cc];
                bh[fn][1] = BsH[t + 4][cc];
                bl[fn][0] = BsL[t    ][cc];
                bl[fn][1] = BsL[t + 4][cc];
            }
            #pragma unroll
            for (int fm = 0; fm < 2; fm++)
                #pragma unroll
                for (int fn = 0; fn < 4; fn++) {
                    float* d = acc[fm][fn];
                    asm volatile(
                        "mma.sync.aligned.m16n8k16.row.col.f32.bf16.bf16.f32 "
                        "{%0,%1,%2,%3}, {%4,%5,%6,%7}, {%8,%9}, {%0,%1,%2,%3};"
                        : "+f"(d[0]), "+f"(d[1]), "+f"(d[2]), "+f"(d[3])
                        : "r"(al[fm][0]), "r"(al[fm][1]), "r"(al[fm][2]), "r"(al[fm][3]),
                          "r"(bh[fn][0]), "r"(bh[fn][1]));
                    asm volatile(
                        "mma.sync.aligned.m16n8k16.row.col.f32.bf16.bf16.f32 "
                        "{%0,%1,%2,%3}, {%4,%5,%6,%7}, {%8,%9}, {%0,%1,%2,%3};"
                        : "+f"(d[0]), "+f"(d[1]), "+f"(d[2]), "+f"(d[3])
                        : "r"(ah[fm][0]), "r"(ah[fm][1]), "r"(ah[fm][2]), "r"(ah[fm][3]),
                          "r"(bl[fn][0]), "r"(bl[fn][1]));
                    asm volatile(
                        "mma.sync.aligned.m16n8k16.row.col.f32.bf16.bf16.f32 "
                        "{%0,%1,%2,%3}, {%4,%5,%6,%7}, {%8,%9}, {%0,%1,%2,%3};"
                        : "+f"(d[0]), "+f"(d[1]), "+f"(d[2]), "+f"(d[3])
                        : "r"(ah[fm][0]), "r"(ah[fm][1]), "r"(ah[fm][2]), "r"(ah[fm][3]),
                          "r"(bh[fn][0]), "r"(bh[fn][1]));
                }
        }
        __syncthreads();
    }

    #pragma unroll
    for (int fm = 0; fm < 2; fm++) {
        int row0 = brow + wm * 32 + fm * 16 + (lane >> 2);
        #pragma unroll
        for (int half = 0; half < 2; half++) {
            int row = row0 + half * 8;
            if (row >= M) continue;
            #pragma unroll
            for (int fn = 0; fn < 4; fn++) {
                int col = bcol + wn * 32 + fn * 8 + 2 * (lane & 3);
                *(float2*)(C + (size_t)row * Nc + col) =
                    make_float2(acc[fm][fn][half * 2 + 0], acc[fm][fn][half * 2 + 1]);
            }
        }
    }
}

// ---------------------------------------------------------------------------
// CSR gather aggregation: warp per node, no atomics.
// out[node] = bias + dinv^2 * hw[node] + sum_in (dinv[n]*dinv[s]) * hw[s]
// DST: 1 = g_h, 2 = g_h2
// ---------------------------------------------------------------------------
template<int DST>
__global__ void k_agg_gather(const float* bias) {
    int gtid = blockIdx.x * blockDim.x + threadIdx.x;
    int node = gtid >> 5;
    int lane = gtid & 31;
    if (node >= NN) return;

    float di = g_dinv[node];
    float ws = di * di;
    const float4* hw = g_hw4 + (size_t)node * (HH / 4);
    float4 b0 = ((const float4*)bias)[lane];
    float4 b1 = ((const float4*)bias)[lane + 32];
    float4 v0 = hw[lane];
    float4 v1 = hw[lane + 32];
    float4 a0 = make_float4(fmaf(ws, v0.x, b0.x), fmaf(ws, v0.y, b0.y),
                            fmaf(ws, v0.z, b0.z), fmaf(ws, v0.w, b0.w));
    float4 a1 = make_float4(fmaf(ws, v1.x, b1.x), fmaf(ws, v1.y, b1.y),
                            fmaf(ws, v1.z, b1.z), fmaf(ws, v1.w, b1.w));

    int e0 = g_off[node], e1 = g_off[node + 1];
    for (int i = e0; i < e1; i++) {
        int s = g_csr[i];
        float w = di * g_dinv[s];
        const float4* hs = g_hw4 + (size_t)s * (HH / 4);
        float4 u0 = hs[lane];
        float4 u1 = hs[lane + 32];
        a0.x = fmaf(w, u0.x, a0.x); a0.y = fmaf(w, u0.y, a0.y);
        a0.z = fmaf(w, u0.z, a0.z); a0.w = fmaf(w, u0.w, a0.w);
        a1.x = fmaf(w, u1.x, a1.x); a1.y = fmaf(w, u1.y, a1.y);
        a1.z = fmaf(w, u1.z, a1.z); a1.w = fmaf(w, u1.w, a1.w);
    }

    float4* out = ((DST == 1) ? g_h4 : g_h24) + (size_t)node * (HH / 4);
    out[lane]      = a0;
    out[lane + 32] = a1;
}

// ---------------------------------------------------------------------------
// Softmax over K=64, warp per row. d_out layout: [S | logits], each NN*KK.
// ---------------------------------------------------------------------------
__global__ void k_softmax(const float* log_tau, float* out) {
    int gtid = blockIdx.x * blockDim.x + threadIdx.x;
    int row  = gtid >> 5;
    int lane = gtid & 31;
    if (row >= NN) return;
    const float* lg = out + (size_t)NN * KK + (size_t)row * KK;
    float inv_tau = __expf(-log_tau[0]);
    float a = lg[lane] * inv_tau;
    float b = lg[lane + 32] * inv_tau;
    float m = fmaxf(a, b);
    #pragma unroll
    for (int off = 16; off > 0; off >>= 1)
        m = fmaxf(m, __shfl_xor_sync(0xFFFFFFFFu, m, off));
    float e0 = __expf(a - m);
    float e1 = __expf(b - m);
    float s = e0 + e1;
    #pragma unroll
    for (int off = 16; off > 0; off >>= 1)
        s += __shfl_xor_sync(0xFFFFFFFFu, s, off);
    float inv = 1.0f / s;
    float* S = out + (size_t)row * KK;
    S[lane]      = e0 * inv;
    S[lane + 32] = e1 * inv;
}

// ---------------------------------------------------------------------------
extern "C" void kernel_launch(void* const* d_in, const int* in_sizes, int n_in,
                              void* d_out, int out_size) {
    const float* x       = (const float*)d_in[0];
    const int*   ei_raw  = (const int*)d_in[1];
    const float* W1      = (const float*)d_in[2];
    const float* b1      = (const float*)d_in[3];
    const float* W2      = (const float*)d_in[4];
    const float* b2      = (const float*)d_in[5];
    const float* Wk      = (const float*)d_in[6];
    const float* log_tau = (const float*)d_in[7];
    float* out = (float*)d_out;

    dim3 grid_H(HH / 64, (NN + 127) / 128);
    dim3 grid_K(KK / 64, (NN + 127) / 128);
    int agg_blocks = (NN * 32 + 255) / 256;

    // Launch order arranged so the 4th launch (ncu's capture slot) is GEMM1.
    k_detect      <<<1, 32>>>(ei_raw);                         // 1
    k_zero        <<<(NN + 255) / 256, 256>>>();               // 2
    k_deg_count   <<<(NE + 255) / 256, 256>>>(ei_raw);         // 3
    k_mma_gemm<false, 0, 1><<<grid_H, 256>>>(x, W1, nullptr, NN, DD, HH);  // 4 <- profiled
    k_dinv        <<<(NN + 255) / 256, 256>>>();               // 5
    k_scan_reduce <<<SCAN_NB, SCAN_B>>>();                     // 6
    k_scan_bases  <<<1, 512>>>();                              // 7
    k_scan_offsets<<<SCAN_NB, SCAN_B>>>();                     // 8
    k_fill        <<<(NE + 255) / 256, 256>>>(ei_raw);         // 9

    // Layer 1 aggregation (needs GEMM1 + dinv + CSR)
    k_agg_gather<1><<<agg_blocks, 256>>>(b1);

    // Layer 2
    k_mma_gemm<true, 1, 1><<<grid_H, 256>>>(nullptr, W2, nullptr, NN, HH, HH);
    k_agg_gather<2><<<agg_blocks, 256>>>(b2);

    // Head
    float* logits = out + (size_t)NN * KK;
    k_mma_gemm<false, 2, 0><<<grid_K, 256>>>(nullptr, Wk, logits, NN, HH, KK);
    k_softmax<<<(NN + 7) / 8, 256>>>(log_tau, out);
}

// round 15
// speedup vs baseline: 1.3107x; 1.1190x over previous
#include <cuda_runtime.h>
#include <cuda_bf16.h>
#include <math.h>

#define NN 100000
#define NE 1600000
#define DD 512
#define HH 256
#define KK 64
#define SCAN_B 256
#define SCAN_NB ((NN + SCAN_B - 1) / SCAN_B)   // 391

// Scratch: __device__ globals, referenced ONLY from device code.
__device__ float4 g_hw4[(size_t)NN * HH / 4];   // GEMM output (message source)
__device__ float4 g_h4 [(size_t)NN * HH / 4];   // hidden state (layer 1)
__device__ float4 g_h24[(size_t)NN * HH / 4];   // hidden state (layer 2)
__device__ float  g_dinv[NN];                   // rsqrt(deg)
__device__ int    g_deg[NN];
__device__ int    g_off[NN + 1];
__device__ int    g_cur[NN];
__device__ int    g_csr[NE];
__device__ int    g_blocksum[SCAN_NB];
__device__ int    g_is64;

// ---------------------------------------------------------------------------
// Edge dtype detection
// ---------------------------------------------------------------------------
__global__ void k_detect(const int* ei_raw) {
    if (threadIdx.x == 0 && blockIdx.x == 0) {
        int all0 = 1;
        for (int i = 0; i < 64; i++)
            if (ei_raw[2 * i + 1] != 0) { all0 = 0; break; }
        g_is64 = all0;
    }
}

__device__ __forceinline__ int edge_at(const int* ei_raw, size_t idx) {
    return g_is64 ? ei_raw[2 * idx] : ei_raw[idx];
}

// ---------------------------------------------------------------------------
// CSR build + norms
// ---------------------------------------------------------------------------
__global__ void k_zero() {
    int i = blockIdx.x * blockDim.x + threadIdx.x;
    if (i < NN) { g_deg[i] = 0; g_cur[i] = 0; }
}

__global__ void k_deg_count(const int* ei_raw) {
    int e = blockIdx.x * blockDim.x + threadIdx.x;
    if (e >= NE) return;
    int d = edge_at(ei_raw, (size_t)NE + e);
    if (d >= 0 && d < NN) atomicAdd(&g_deg[d], 1);
}

__global__ void k_dinv() {
    int i = blockIdx.x * blockDim.x + threadIdx.x;
    if (i < NN) g_dinv[i] = rsqrtf((float)(g_deg[i] + 1));
}

__global__ void k_scan_reduce() {
    __shared__ int sh[SCAN_B];
    int i = blockIdx.x * SCAN_B + threadIdx.x;
    sh[threadIdx.x] = (i < NN) ? g_deg[i] : 0;
    __syncthreads();
    for (int s = SCAN_B / 2; s > 0; s >>= 1) {
        if (threadIdx.x < s) sh[threadIdx.x] += sh[threadIdx.x + s];
        __syncthreads();
    }
    if (threadIdx.x == 0) g_blocksum[blockIdx.x] = sh[0];
}

__global__ void k_scan_bases() {
    __shared__ int sh[512];
    int i = threadIdx.x;
    int v = (i < SCAN_NB) ? g_blocksum[i] : 0;
    sh[i] = v;
    __syncthreads();
    for (int s = 1; s < 512; s <<= 1) {
        int t = (i >= s) ? sh[i - s] : 0;
        __syncthreads();
        sh[i] += t;
        __syncthreads();
    }
    if (i < SCAN_NB) g_blocksum[i] = sh[i] - v;
    if (i == SCAN_NB - 1) g_off[NN] = sh[i];
}

__global__ void k_scan_offsets() {
    __shared__ int sh[SCAN_B];
    int i = blockIdx.x * SCAN_B + threadIdx.x;
    int v = (i < NN) ? g_deg[i] : 0;
    sh[threadIdx.x] = v;
    __syncthreads();
    for (int s = 1; s < SCAN_B; s <<= 1) {
        int t = (threadIdx.x >= s) ? sh[threadIdx.x - s] : 0;
        __syncthreads();
        sh[threadIdx.x] += t;
        __syncthreads();
    }
    if (i < NN) g_off[i] = g_blocksum[blockIdx.x] + sh[threadIdx.x] - v;
}

__global__ void k_fill(const int* ei_raw) {
    int e = blockIdx.x * blockDim.x + threadIdx.x;
    if (e >= NE) return;
    int s = edge_at(ei_raw, (size_t)e);
    int d = edge_at(ei_raw, (size_t)NE + e);
    if ((unsigned)s >= NN || (unsigned)d >= NN) return;
    int pos = g_off[d] + atomicAdd(&g_cur[d], 1);
    g_csr[pos] = s;
}

// ---------------------------------------------------------------------------
// Split-bf16 tensor GEMM with ldmatrix fragment loading.
// Both A and B stored in smem as rows-of-k: [row][k2], PAD=20 u32 (80B)
// rows -> 16B-aligned LDSM rows, conflict-free phases, uint2-able stores.
// acc += lo*hi' + hi*lo' + hi*hi' (fp32 regs). BM=128, BN=64, BK=32,
// 256 thr (8 warps 4m x 2n), warp tile 32x32.
// ---------------------------------------------------------------------------
__device__ __forceinline__ void split2(float a, float b, unsigned& hi, unsigned& lo) {
    __nv_bfloat16 ha = __float2bfloat16(a);
    __nv_bfloat16 hb = __float2bfloat16(b);
    __nv_bfloat16 la = __float2bfloat16(a - __bfloat162float(ha));
    __nv_bfloat16 lb = __float2bfloat16(b - __bfloat162float(hb));
    hi = (unsigned)__bfloat16_as_ushort(ha) | ((unsigned)__bfloat16_as_ushort(hb) << 16);
    lo = (unsigned)__bfloat16_as_ushort(la) | ((unsigned)__bfloat16_as_ushort(lb) << 16);
}

__device__ __forceinline__ void ldsm_x4(unsigned& r0, unsigned& r1,
                                        unsigned& r2, unsigned& r3, unsigned addr) {
    asm volatile("ldmatrix.sync.aligned.m8n8.x4.shared.b16 {%0,%1,%2,%3}, [%4];"
                 : "=r"(r0), "=r"(r1), "=r"(r2), "=r"(r3) : "r"(addr));
}

template<bool RELU_A, int A_SRC, int C_DST>
__global__ void k_mma_gemm(const float* Aext, const float* B, float* Cext,
                           int M, int Kc, int Nc) {
    const float* A = (A_SRC == 1) ? (const float*)g_h4
                   : (A_SRC == 2) ? (const float*)g_h24 : Aext;
    float*       C = (C_DST == 1) ? (float*)g_hw4       : Cext;

    const int BM = 128, BN = 64, BK = 32, PAD = 20;
    __shared__ unsigned AsH[BM * PAD], AsL[BM * PAD];
    __shared__ unsigned BsH[BN * PAD], BsL[BN * PAD];

    unsigned aHb = (unsigned)__cvta_generic_to_shared(AsH);
    unsigned aLb = (unsigned)__cvta_generic_to_shared(AsL);
    unsigned bHb = (unsigned)__cvta_generic_to_shared(BsH);
    unsigned bLb = (unsigned)__cvta_generic_to_shared(BsL);

    int tid  = threadIdx.x;
    int wid  = tid >> 5;
    int lane = tid & 31;
    int wm   = wid >> 1;
    int wn   = wid & 1;
    int brow = blockIdx.y * BM;
    int bcol = blockIdx.x * BN;

    float acc[2][4][4];
    #pragma unroll
    for (int i = 0; i < 2; i++)
        #pragma unroll
        for (int j = 0; j < 4; j++)
            #pragma unroll
            for (int r = 0; r < 4; r++) acc[i][j][r] = 0.0f;

    int mi = lane >> 3;           // ldmatrix quadrant
    int ii = lane & 7;

    for (int k0 = 0; k0 < Kc; k0 += BK) {
        // A tile: 128x32 floats = 1024 float4, 4 per thread; uint2 stores
        #pragma unroll
        for (int l = 0; l < 4; l++) {
            int f  = tid + l * 256;
            int ar = f >> 3;              // 0..127
            int fq = f & 7;               // float4 slot within row
            int gr = brow + ar;
            float4 v = make_float4(0.f, 0.f, 0.f, 0.f);
            if (gr < M) v = *(const float4*)(A + (size_t)gr * Kc + k0 + (fq << 2));
            if (RELU_A) {
                v.x = fmaxf(v.x, 0.f); v.y = fmaxf(v.y, 0.f);
                v.z = fmaxf(v.z, 0.f); v.w = fmaxf(v.w, 0.f);
            }
            unsigned h0, l0, h1, l1;
            split2(v.x, v.y, h0, l0);
            split2(v.z, v.w, h1, l1);
            int k2 = fq << 1;
            *(uint2*)&AsH[ar * PAD + k2] = make_uint2(h0, h1);
            *(uint2*)&AsL[ar * PAD + k2] = make_uint2(l0, l1);
        }
        // B tile: 32x64 floats; store TRANSPOSED as Bs[n][k2]
        {
            int r2 = tid >> 4;            // k2 row 0..15
            int bc = (tid & 15) << 2;     // n col 0..60
            float4 v0 = *(const float4*)(B + (size_t)(k0 + 2 * r2    ) * Nc + bcol + bc);
            float4 v1 = *(const float4*)(B + (size_t)(k0 + 2 * r2 + 1) * Nc + bcol + bc);
            unsigned h, lo;
            split2(v0.x, v1.x, h, lo);
            BsH[(bc + 0) * PAD + r2] = h;  BsL[(bc + 0) * PAD + r2] = lo;
            split2(v0.y, v1.y, h, lo);
            BsH[(bc + 1) * PAD + r2] = h;  BsL[(bc + 1) * PAD + r2] = lo;
            split2(v0.z, v1.z, h, lo);
            BsH[(bc + 2) * PAD + r2] = h;  BsL[(bc + 2) * PAD + r2] = lo;
            split2(v0.w, v1.w, h, lo);
            BsH[(bc + 3) * PAD + r2] = h;  BsL[(bc + 3) * PAD + r2] = lo;
        }
        __syncthreads();

        #pragma unroll
        for (int sub = 0; sub < 2; sub++) {
            int t0 = sub << 3;            // k2 base within BK

            unsigned ah[2][4], al[2][4];
            #pragma unroll
            for (int fm = 0; fm < 2; fm++) {
                int row  = wm * 32 + fm * 16 + ((mi & 1) << 3) + ii;
                int colA = t0 + ((mi >> 1) << 2);
                unsigned off = (unsigned)(row * PAD + colA) << 2;
                ldsm_x4(ah[fm][0], ah[fm][1], ah[fm][2], ah[fm][3], aHb + off);
                ldsm_x4(al[fm][0], al[fm][1], al[fm][2], al[fm][3], aLb + off);
            }
            unsigned bh[4][2], bl[4][2];
            #pragma unroll
            for (int fp = 0; fp < 2; fp++) {
                int nrow = wn * 32 + fp * 16 + ((mi >> 1) << 3) + ii;
                int colB = t0 + ((mi & 1) << 2);
                unsigned off = (unsigned)(nrow * PAD + colB) << 2;
                ldsm_x4(bh[2 * fp][0], bh[2 * fp][1],
                        bh[2 * fp + 1][0], bh[2 * fp + 1][1], bHb + off);
                ldsm_x4(bl[2 * fp][0], bl[2 * fp][1],
                        bl[2 * fp + 1][0], bl[2 * fp + 1][1], bLb + off);
            }

            #pragma unroll
            for (int fm = 0; fm < 2; fm++)
                #pragma unroll
                for (int fn = 0; fn < 4; fn++) {
                    float* d = acc[fm][fn];
                    asm volatile(
                        "mma.sync.aligned.m16n8k16.row.col.f32.bf16.bf16.f32 "
                        "{%0,%1,%2,%3}, {%4,%5,%6,%7}, {%8,%9}, {%0,%1,%2,%3};"
                        : "+f"(d[0]), "+f"(d[1]), "+f"(d[2]), "+f"(d[3])
                        : "r"(al[fm][0]), "r"(al[fm][1]), "r"(al[fm][2]), "r"(al[fm][3]),
                          "r"(bh[fn][0]), "r"(bh[fn][1]));
                    asm volatile(
                        "mma.sync.aligned.m16n8k16.row.col.f32.bf16.bf16.f32 "
                        "{%0,%1,%2,%3}, {%4,%5,%6,%7}, {%8,%9}, {%0,%1,%2,%3};"
                        : "+f"(d[0]), "+f"(d[1]), "+f"(d[2]), "+f"(d[3])
                        : "r"(ah[fm][0]), "r"(ah[fm][1]), "r"(ah[fm][2]), "r"(ah[fm][3]),
                          "r"(bl[fn][0]), "r"(bl[fn][1]));
                    asm volatile(
                        "mma.sync.aligned.m16n8k16.row.col.f32.bf16.bf16.f32 "
                        "{%0,%1,%2,%3}, {%4,%5,%6,%7}, {%8,%9}, {%0,%1,%2,%3};"
                        : "+f"(d[0]), "+f"(d[1]), "+f"(d[2]), "+f"(d[3])
                        : "r"(ah[fm][0]), "r"(ah[fm][1]), "r"(ah[fm][2]), "r"(ah[fm][3]),
                          "r"(bh[fn][0]), "r"(bh[fn][1]));
                }
        }
        __syncthreads();
    }

    #pragma unroll
    for (int fm = 0; fm < 2; fm++) {
        int row0 = brow + wm * 32 + fm * 16 + (lane >> 2);
        #pragma unroll
        for (int half = 0; half < 2; half++) {
            int row = row0 + half * 8;
            if (row >= M) continue;
            #pragma unroll
            for (int fn = 0; fn < 4; fn++) {
                int col = bcol + wn * 32 + fn * 8 + 2 * (lane & 3);
                *(float2*)(C + (size_t)row * Nc + col) =
                    make_float2(acc[fm][fn][half * 2 + 0], acc[fm][fn][half * 2 + 1]);
            }
        }
    }
}

// ---------------------------------------------------------------------------
// CSR gather aggregation: warp per node, no atomics.
// ---------------------------------------------------------------------------
template<int DST>
__global__ void k_agg_gather(const float* bias) {
    int gtid = blockIdx.x * blockDim.x + threadIdx.x;
    int node = gtid >> 5;
    int lane = gtid & 31;
    if (node >= NN) return;

    float di = g_dinv[node];
    float ws = di * di;
    const float4* hw = g_hw4 + (size_t)node * (HH / 4);
    float4 b0 = ((const float4*)bias)[lane];
    float4 b1 = ((const float4*)bias)[lane + 32];
    float4 v0 = hw[lane];
    float4 v1 = hw[lane + 32];
    float4 a0 = make_float4(fmaf(ws, v0.x, b0.x), fmaf(ws, v0.y, b0.y),
                            fmaf(ws, v0.z, b0.z), fmaf(ws, v0.w, b0.w));
    float4 a1 = make_float4(fmaf(ws, v1.x, b1.x), fmaf(ws, v1.y, b1.y),
                            fmaf(ws, v1.z, b1.z), fmaf(ws, v1.w, b1.w));

    int e0 = g_off[node], e1 = g_off[node + 1];
    for (int i = e0; i < e1; i++) {
        int s = g_csr[i];
        float w = di * g_dinv[s];
        const float4* hs = g_hw4 + (size_t)s * (HH / 4);
        float4 u0 = hs[lane];
        float4 u1 = hs[lane + 32];
        a0.x = fmaf(w, u0.x, a0.x); a0.y = fmaf(w, u0.y, a0.y);
        a0.z = fmaf(w, u0.z, a0.z); a0.w = fmaf(w, u0.w, a0.w);
        a1.x = fmaf(w, u1.x, a1.x); a1.y = fmaf(w, u1.y, a1.y);
        a1.z = fmaf(w, u1.z, a1.z); a1.w = fmaf(w, u1.w, a1.w);
    }

    float4* out = ((DST == 1) ? g_h4 : g_h24) + (size_t)node * (HH / 4);
    out[lane]      = a0;
    out[lane + 32] = a1;
}

// ---------------------------------------------------------------------------
// Softmax over K=64, warp per row. d_out layout: [S | logits], each NN*KK.
// ---------------------------------------------------------------------------
__global__ void k_softmax(const float* log_tau, float* out) {
    int gtid = blockIdx.x * blockDim.x + threadIdx.x;
    int row  = gtid >> 5;
    int lane = gtid & 31;
    if (row >= NN) return;
    const float* lg = out + (size_t)NN * KK + (size_t)row * KK;
    float inv_tau = __expf(-log_tau[0]);
    float a = lg[lane] * inv_tau;
    float b = lg[lane + 32] * inv_tau;
    float m = fmaxf(a, b);
    #pragma unroll
    for (int off = 16; off > 0; off >>= 1)
        m = fmaxf(m, __shfl_xor_sync(0xFFFFFFFFu, m, off));
    float e0 = __expf(a - m);
    float e1 = __expf(b - m);
    float s = e0 + e1;
    #pragma unroll
    for (int off = 16; off > 0; off >>= 1)
        s += __shfl_xor_sync(0xFFFFFFFFu, s, off);
    float inv = 1.0f / s;
    float* S = out + (size_t)row * KK;
    S[lane]      = e0 * inv;
    S[lane + 32] = e1 * inv;
}

// ---------------------------------------------------------------------------
extern "C" void kernel_launch(void* const* d_in, const int* in_sizes, int n_in,
                              void* d_out, int out_size) {
    const float* x       = (const float*)d_in[0];
    const int*   ei_raw  = (const int*)d_in[1];
    const float* W1      = (const float*)d_in[2];
    const float* b1      = (const float*)d_in[3];
    const float* W2      = (const float*)d_in[4];
    const float* b2      = (const float*)d_in[5];
    const float* Wk      = (const float*)d_in[6];
    const float* log_tau = (const float*)d_in[7];
    float* out = (float*)d_out;

    dim3 grid_H(HH / 64, (NN + 127) / 128);
    dim3 grid_K(KK / 64, (NN + 127) / 128);
    int agg_blocks = (NN * 32 + 255) / 256;

    // Launch order keeps GEMM1 as the 4th launch (ncu capture slot).
    k_detect      <<<1, 32>>>(ei_raw);                         // 1
    k_zero        <<<(NN + 255) / 256, 256>>>();               // 2
    k_deg_count   <<<(NE + 255) / 256, 256>>>(ei_raw);         // 3
    k_mma_gemm<false, 0, 1><<<grid_H, 256>>>(x, W1, nullptr, NN, DD, HH);  // 4 <- profiled
    k_dinv        <<<(NN + 255) / 256, 256>>>();               // 5
    k_scan_reduce <<<SCAN_NB, SCAN_B>>>();                     // 6
    k_scan_bases  <<<1, 512>>>();                              // 7
    k_scan_offsets<<<SCAN_NB, SCAN_B>>>();                     // 8
    k_fill        <<<(NE + 255) / 256, 256>>>(ei_raw);         // 9

    // Layer 1 aggregation
    k_agg_gather<1><<<agg_blocks, 256>>>(b1);

    // Layer 2
    k_mma_gemm<true, 1, 1><<<grid_H, 256>>>(nullptr, W2, nullptr, NN, HH, HH);
    k_agg_gather<2><<<agg_blocks, 256>>>(b2);

    // Head
    float* logits = out + (size_t)NN * KK;
    k_mma_gemm<false, 2, 0><<<grid_K, 256>>>(nullptr, Wk, logits, NN, HH, KK);
    k_softmax<<<(NN + 7) / 8, 256>>>(log_tau, out);
}

// round 16
// speedup vs baseline: 1.4314x; 1.0920x over previous
#include <cuda_runtime.h>
#include <cuda_bf16.h>
#include <math.h>

#define NN 100000
#define NE 1600000
#define DD 512
#define HH 256
#define KK 64
#define SCAN_B 256
#define SCAN_NB ((NN + SCAN_B - 1) / SCAN_B)   // 391

// Scratch: __device__ globals, referenced ONLY from device code.
__device__ float4 g_hw4[(size_t)NN * HH / 4];   // GEMM output (message source)
__device__ float4 g_h4 [(size_t)NN * HH / 4];   // hidden state (layer 1)
__device__ float4 g_h24[(size_t)NN * HH / 4];   // hidden state (layer 2)
__device__ float  g_dinv[NN];                   // rsqrt(deg)
__device__ int    g_deg[NN];
__device__ int    g_off[NN + 1];
__device__ int    g_cur[NN];
__device__ int    g_csr[NE];
__device__ int    g_blocksum[SCAN_NB];
__device__ int    g_is64;

// ---------------------------------------------------------------------------
// Edge dtype detection
// ---------------------------------------------------------------------------
__global__ void k_detect(const int* ei_raw) {
    if (threadIdx.x == 0 && blockIdx.x == 0) {
        int all0 = 1;
        for (int i = 0; i < 64; i++)
            if (ei_raw[2 * i + 1] != 0) { all0 = 0; break; }
        g_is64 = all0;
    }
}

__device__ __forceinline__ int edge_at(const int* ei_raw, size_t idx) {
    return g_is64 ? ei_raw[2 * idx] : ei_raw[idx];
}

// ---------------------------------------------------------------------------
// CSR build + norms
// ---------------------------------------------------------------------------
__global__ void k_zero() {
    int i = blockIdx.x * blockDim.x + threadIdx.x;
    if (i < NN) { g_deg[i] = 0; g_cur[i] = 0; }
}

__global__ void k_deg_count(const int* ei_raw) {
    int e = blockIdx.x * blockDim.x + threadIdx.x;
    if (e >= NE) return;
    int d = edge_at(ei_raw, (size_t)NE + e);
    if (d >= 0 && d < NN) atomicAdd(&g_deg[d], 1);
}

__global__ void k_dinv() {
    int i = blockIdx.x * blockDim.x + threadIdx.x;
    if (i < NN) g_dinv[i] = rsqrtf((float)(g_deg[i] + 1));
}

__global__ void k_scan_reduce() {
    __shared__ int sh[SCAN_B];
    int i = blockIdx.x * SCAN_B + threadIdx.x;
    sh[threadIdx.x] = (i < NN) ? g_deg[i] : 0;
    __syncthreads();
    for (int s = SCAN_B / 2; s > 0; s >>= 1) {
        if (threadIdx.x < s) sh[threadIdx.x] += sh[threadIdx.x + s];
        __syncthreads();
    }
    if (threadIdx.x == 0) g_blocksum[blockIdx.x] = sh[0];
}

__global__ void k_scan_bases() {
    __shared__ int sh[512];
    int i = threadIdx.x;
    int v = (i < SCAN_NB) ? g_blocksum[i] : 0;
    sh[i] = v;
    __syncthreads();
    for (int s = 1; s < 512; s <<= 1) {
        int t = (i >= s) ? sh[i - s] : 0;
        __syncthreads();
        sh[i] += t;
        __syncthreads();
    }
    if (i < SCAN_NB) g_blocksum[i] = sh[i] - v;
    if (i == SCAN_NB - 1) g_off[NN] = sh[i];
}

__global__ void k_scan_offsets() {
    __shared__ int sh[SCAN_B];
    int i = blockIdx.x * SCAN_B + threadIdx.x;
    int v = (i < NN) ? g_deg[i] : 0;
    sh[threadIdx.x] = v;
    __syncthreads();
    for (int s = 1; s < SCAN_B; s <<= 1) {
        int t = (threadIdx.x >= s) ? sh[threadIdx.x - s] : 0;
        __syncthreads();
        sh[threadIdx.x] += t;
        __syncthreads();
    }
    if (i < NN) g_off[i] = g_blocksum[blockIdx.x] + sh[threadIdx.x] - v;
}

__global__ void k_fill(const int* ei_raw) {
    int e = blockIdx.x * blockDim.x + threadIdx.x;
    if (e >= NE) return;
    int s = edge_at(ei_raw, (size_t)e);
    int d = edge_at(ei_raw, (size_t)NE + e);
    if ((unsigned)s >= NN || (unsigned)d >= NN) return;
    int pos = g_off[d] + atomicAdd(&g_cur[d], 1);
    g_csr[pos] = s;
}

// ---------------------------------------------------------------------------
// Split-bf16 tensor GEMM.
// A in smem as k-pair rows [m][k2], PAD=20 u32 -> non-trans LDSM (validated).
// B in smem as b16 [k][n], row pad 72 b16 (144B = 9x16B): conflict-free
// vectorized stores along n, conflict-free ldmatrix.x4.trans.b16 loads.
// acc += lo*hi' + hi*lo' + hi*hi' (fp32 regs). BM=128, BN=64, BK=32,
// 256 thr (8 warps 4m x 2n), warp tile 32x32.
// ---------------------------------------------------------------------------
__device__ __forceinline__ void split2(float a, float b, unsigned& hi, unsigned& lo) {
    __nv_bfloat16 ha = __float2bfloat16(a);
    __nv_bfloat16 hb = __float2bfloat16(b);
    __nv_bfloat16 la = __float2bfloat16(a - __bfloat162float(ha));
    __nv_bfloat16 lb = __float2bfloat16(b - __bfloat162float(hb));
    hi = (unsigned)__bfloat16_as_ushort(ha) | ((unsigned)__bfloat16_as_ushort(hb) << 16);
    lo = (unsigned)__bfloat16_as_ushort(la) | ((unsigned)__bfloat16_as_ushort(lb) << 16);
}

__device__ __forceinline__ void ldsm_x4(unsigned& r0, unsigned& r1,
                                        unsigned& r2, unsigned& r3, unsigned addr) {
    asm volatile("ldmatrix.sync.aligned.m8n8.x4.shared.b16 {%0,%1,%2,%3}, [%4];"
                 : "=r"(r0), "=r"(r1), "=r"(r2), "=r"(r3) : "r"(addr));
}
__device__ __forceinline__ void ldsm_x4_t(unsigned& r0, unsigned& r1,
                                          unsigned& r2, unsigned& r3, unsigned addr) {
    asm volatile("ldmatrix.sync.aligned.m8n8.x4.trans.shared.b16 {%0,%1,%2,%3}, [%4];"
                 : "=r"(r0), "=r"(r1), "=r"(r2), "=r"(r3) : "r"(addr));
}

template<bool RELU_A, int A_SRC, int C_DST>
__global__ void k_mma_gemm(const float* Aext, const float* B, float* Cext,
                           int M, int Kc, int Nc) {
    const float* A = (A_SRC == 1) ? (const float*)g_h4
                   : (A_SRC == 2) ? (const float*)g_h24 : Aext;
    float*       C = (C_DST == 1) ? (float*)g_hw4       : Cext;

    const int BM = 128, BN = 64, BK = 32, PAD = 20, BPAD = 72;
    __shared__ unsigned AsH[BM * PAD], AsL[BM * PAD];
    __shared__ unsigned short BsH[BK * BPAD], BsL[BK * BPAD];

    unsigned aHb = (unsigned)__cvta_generic_to_shared(AsH);
    unsigned aLb = (unsigned)__cvta_generic_to_shared(AsL);
    unsigned bHb = (unsigned)__cvta_generic_to_shared(BsH);
    unsigned bLb = (unsigned)__cvta_generic_to_shared(BsL);

    int tid  = threadIdx.x;
    int wid  = tid >> 5;
    int lane = tid & 31;
    int wm   = wid >> 1;
    int wn   = wid & 1;
    int brow = blockIdx.y * BM;
    int bcol = blockIdx.x * BN;

    float acc[2][4][4];
    #pragma unroll
    for (int i = 0; i < 2; i++)
        #pragma unroll
        for (int j = 0; j < 4; j++)
            #pragma unroll
            for (int r = 0; r < 4; r++) acc[i][j][r] = 0.0f;

    int mi = lane >> 3;           // ldmatrix quadrant
    int ii = lane & 7;

    for (int k0 = 0; k0 < Kc; k0 += BK) {
        // A tile: 128x32 floats = 1024 float4, 4 per thread; uint2 stores
        #pragma unroll
        for (int l = 0; l < 4; l++) {
            int f  = tid + l * 256;
            int ar = f >> 3;              // 0..127
            int fq = f & 7;               // float4 slot within row
            int gr = brow + ar;
            float4 v = make_float4(0.f, 0.f, 0.f, 0.f);
            if (gr < M) v = *(const float4*)(A + (size_t)gr * Kc + k0 + (fq << 2));
            if (RELU_A) {
                v.x = fmaxf(v.x, 0.f); v.y = fmaxf(v.y, 0.f);
                v.z = fmaxf(v.z, 0.f); v.w = fmaxf(v.w, 0.f);
            }
            unsigned h0, l0, h1, l1;
            split2(v.x, v.y, h0, l0);
            split2(v.z, v.w, h1, l1);
            int k2 = fq << 1;
            *(uint2*)&AsH[ar * PAD + k2] = make_uint2(h0, h1);
            *(uint2*)&AsL[ar * PAD + k2] = make_uint2(l0, l1);
        }
        // B tile: 32x64 floats; store as b16 [k][n] rows (n-pairs packed in u32)
        {
            int r2 = tid >> 4;            // 0..15 -> k rows 2r2, 2r2+1
            int bc = (tid & 15) << 2;     // n col 0..60
            float4 v0 = *(const float4*)(B + (size_t)(k0 + 2 * r2    ) * Nc + bcol + bc);
            float4 v1 = *(const float4*)(B + (size_t)(k0 + 2 * r2 + 1) * Nc + bcol + bc);
            unsigned h01, l01, h23, l23;
            split2(v0.x, v0.y, h01, l01);      // n-pair pack
            split2(v0.z, v0.w, h23, l23);
            *(uint2*)&BsH[(2 * r2) * BPAD + bc] = make_uint2(h01, h23);
            *(uint2*)&BsL[(2 * r2) * BPAD + bc] = make_uint2(l01, l23);
            split2(v1.x, v1.y, h01, l01);
            split2(v1.z, v1.w, h23, l23);
            *(uint2*)&BsH[(2 * r2 + 1) * BPAD + bc] = make_uint2(h01, h23);
            *(uint2*)&BsL[(2 * r2 + 1) * BPAD + bc] = make_uint2(l01, l23);
        }
        __syncthreads();

        #pragma unroll
        for (int sub = 0; sub < 2; sub++) {
            int t0 = sub << 3;            // k2 base within BK (A side)

            unsigned ah[2][4], al[2][4];
            #pragma unroll
            for (int fm = 0; fm < 2; fm++) {
                int row  = wm * 32 + fm * 16 + ((mi & 1) << 3) + ii;
                int colA = t0 + ((mi >> 1) << 2);
                unsigned off = (unsigned)(row * PAD + colA) << 2;
                ldsm_x4(ah[fm][0], ah[fm][1], ah[fm][2], ah[fm][3], aHb + off);
                ldsm_x4(al[fm][0], al[fm][1], al[fm][2], al[fm][3], aLb + off);
            }
            // B via trans LDSM on [k][n] layout:
            // matrix (mi): koct = mi&1, noct = fp*2 + (mi>>1)
            unsigned bh[4][2], bl[4][2];
            #pragma unroll
            for (int fp = 0; fp < 2; fp++) {
                int kk = (sub << 4) + ((mi & 1) << 3) + ii;
                int nn = wn * 32 + fp * 16 + ((mi >> 1) << 3);
                unsigned off = (unsigned)(kk * BPAD + nn) << 1;
                ldsm_x4_t(bh[2 * fp][0], bh[2 * fp][1],
                          bh[2 * fp + 1][0], bh[2 * fp + 1][1], bHb + off);
                ldsm_x4_t(bl[2 * fp][0], bl[2 * fp][1],
                          bl[2 * fp + 1][0], bl[2 * fp + 1][1], bLb + off);
            }

            #pragma unroll
            for (int fm = 0; fm < 2; fm++)
                #pragma unroll
                for (int fn = 0; fn < 4; fn++) {
                    float* d = acc[fm][fn];
                    asm volatile(
                        "mma.sync.aligned.m16n8k16.row.col.f32.bf16.bf16.f32 "
                        "{%0,%1,%2,%3}, {%4,%5,%6,%7}, {%8,%9}, {%0,%1,%2,%3};"
                        : "+f"(d[0]), "+f"(d[1]), "+f"(d[2]), "+f"(d[3])
                        : "r"(al[fm][0]), "r"(al[fm][1]), "r"(al[fm][2]), "r"(al[fm][3]),
                          "r"(bh[fn][0]), "r"(bh[fn][1]));
                    asm volatile(
                        "mma.sync.aligned.m16n8k16.row.col.f32.bf16.bf16.f32 "
                        "{%0,%1,%2,%3}, {%4,%5,%6,%7}, {%8,%9}, {%0,%1,%2,%3};"
                        : "+f"(d[0]), "+f"(d[1]), "+f"(d[2]), "+f"(d[3])
                        : "r"(ah[fm][0]), "r"(ah[fm][1]), "r"(ah[fm][2]), "r"(ah[fm][3]),
                          "r"(bl[fn][0]), "r"(bl[fn][1]));
                    asm volatile(
                        "mma.sync.aligned.m16n8k16.row.col.f32.bf16.bf16.f32 "
                        "{%0,%1,%2,%3}, {%4,%5,%6,%7}, {%8,%9}, {%0,%1,%2,%3};"
                        : "+f"(d[0]), "+f"(d[1]), "+f"(d[2]), "+f"(d[3])
                        : "r"(ah[fm][0]), "r"(ah[fm][1]), "r"(ah[fm][2]), "r"(ah[fm][3]),
                          "r"(bh[fn][0]), "r"(bh[fn][1]));
                }
        }
        __syncthreads();
    }

    #pragma unroll
    for (int fm = 0; fm < 2; fm++) {
        int row0 = brow + wm * 32 + fm * 16 + (lane >> 2);
        #pragma unroll
        for (int half = 0; half < 2; half++) {
            int row = row0 + half * 8;
            if (row >= M) continue;
            #pragma unroll
            for (int fn = 0; fn < 4; fn++) {
                int col = bcol + wn * 32 + fn * 8 + 2 * (lane & 3);
                *(float2*)(C + (size_t)row * Nc + col) =
                    make_float2(acc[fm][fn][half * 2 + 0], acc[fm][fn][half * 2 + 1]);
            }
        }
    }
}

// ---------------------------------------------------------------------------
// CSR gather aggregation: warp per node, no atomics.
// ---------------------------------------------------------------------------
template<int DST>
__global__ void k_agg_gather(const float* bias) {
    int gtid = blockIdx.x * blockDim.x + threadIdx.x;
    int node = gtid >> 5;
    int lane = gtid & 31;
    if (node >= NN) return;

    float di = g_dinv[node];
    float ws = di * di;
    const float4* hw = g_hw4 + (size_t)node * (HH / 4);
    float4 b0 = ((const float4*)bias)[lane];
    float4 b1 = ((const float4*)bias)[lane + 32];
    float4 v0 = hw[lane];
    float4 v1 = hw[lane + 32];
    float4 a0 = make_float4(fmaf(ws, v0.x, b0.x), fmaf(ws, v0.y, b0.y),
                            fmaf(ws, v0.z, b0.z), fmaf(ws, v0.w, b0.w));
    float4 a1 = make_float4(fmaf(ws, v1.x, b1.x), fmaf(ws, v1.y, b1.y),
                            fmaf(ws, v1.z, b1.z), fmaf(ws, v1.w, b1.w));

    int e0 = g_off[node], e1 = g_off[node + 1];
    for (int i = e0; i < e1; i++) {
        int s = g_csr[i];
        float w = di * g_dinv[s];
        const float4* hs = g_hw4 + (size_t)s * (HH / 4);
        float4 u0 = hs[lane];
        float4 u1 = hs[lane + 32];
        a0.x = fmaf(w, u0.x, a0.x); a0.y = fmaf(w, u0.y, a0.y);
        a0.z = fmaf(w, u0.z, a0.z); a0.w = fmaf(w, u0.w, a0.w);
        a1.x = fmaf(w, u1.x, a1.x); a1.y = fmaf(w, u1.y, a1.y);
        a1.z = fmaf(w, u1.z, a1.z); a1.w = fmaf(w, u1.w, a1.w);
    }

    float4* out = ((DST == 1) ? g_h4 : g_h24) + (size_t)node * (HH / 4);
    out[lane]      = a0;
    out[lane + 32] = a1;
}

// ---------------------------------------------------------------------------
// Softmax over K=64, warp per row. d_out layout: [S | logits], each NN*KK.
// ---------------------------------------------------------------------------
__global__ void k_softmax(const float* log_tau, float* out) {
    int gtid = blockIdx.x * blockDim.x + threadIdx.x;
    int row  = gtid >> 5;
    int lane = gtid & 31;
    if (row >= NN) return;
    const float* lg = out + (size_t)NN * KK + (size_t)row * KK;
    float inv_tau = __expf(-log_tau[0]);
    float a = lg[lane] * inv_tau;
    float b = lg[lane + 32] * inv_tau;
    float m = fmaxf(a, b);
    #pragma unroll
    for (int off = 16; off > 0; off >>= 1)
        m = fmaxf(m, __shfl_xor_sync(0xFFFFFFFFu, m, off));
    float e0 = __expf(a - m);
    float e1 = __expf(b - m);
    float s = e0 + e1;
    #pragma unroll
    for (int off = 16; off > 0; off >>= 1)
        s += __shfl_xor_sync(0xFFFFFFFFu, s, off);
    float inv = 1.0f / s;
    float* S = out + (size_t)row * KK;
    S[lane]      = e0 * inv;
    S[lane + 32] = e1 * inv;
}

// ---------------------------------------------------------------------------
extern "C" void kernel_launch(void* const* d_in, const int* in_sizes, int n_in,
                              void* d_out, int out_size) {
    const float* x       = (const float*)d_in[0];
    const int*   ei_raw  = (const int*)d_in[1];
    const float* W1      = (const float*)d_in[2];
    const float* b1      = (const float*)d_in[3];
    const float* W2      = (const float*)d_in[4];
    const float* b2      = (const float*)d_in[5];
    const float* Wk      = (const float*)d_in[6];
    const float* log_tau = (const float*)d_in[7];
    float* out = (float*)d_out;

    dim3 grid_H(HH / 64, (NN + 127) / 128);
    dim3 grid_K(KK / 64, (NN + 127) / 128);
    int agg_blocks = (NN * 32 + 255) / 256;

    // Launch order keeps GEMM1 as the 4th launch (ncu capture slot).
    k_detect      <<<1, 32>>>(ei_raw);                         // 1
    k_zero        <<<(NN + 255) / 256, 256>>>();               // 2
    k_deg_count   <<<(NE + 255) / 256, 256>>>(ei_raw);         // 3
    k_mma_gemm<false, 0, 1><<<grid_H, 256>>>(x, W1, nullptr, NN, DD, HH);  // 4 <- profiled
    k_dinv        <<<(NN + 255) / 256, 256>>>();               // 5
    k_scan_reduce <<<SCAN_NB, SCAN_B>>>();                     // 6
    k_scan_bases  <<<1, 512>>>();                              // 7
    k_scan_offsets<<<SCAN_NB, SCAN_B>>>();                     // 8
    k_fill        <<<(NE + 255) / 256, 256>>>(ei_raw);         // 9

    // Layer 1 aggregation
    k_agg_gather<1><<<agg_blocks, 256>>>(b1);

    // Layer 2
    k_mma_gemm<true, 1, 1><<<grid_H, 256>>>(nullptr, W2, nullptr, NN, HH, HH);
    k_agg_gather<2><<<agg_blocks, 256>>>(b2);

    // Head
    float* logits = out + (size_t)NN * KK;
    k_mma_gemm<false, 2, 0><<<grid_K, 256>>>(nullptr, Wk, logits, NN, HH, KK);
    k_softmax<<<(NN + 7) / 8, 256>>>(log_tau, out);
}

// round 17
// speedup vs baseline: 1.6546x; 1.1559x over previous
#include <cuda_runtime.h>
#include <cuda_bf16.h>
#include <math.h>

#define NN 100000
#define NE 1600000
#define DD 512
#define HH 256
#define KK 64
#define SCAN_B 256
#define SCAN_NB ((NN + SCAN_B - 1) / SCAN_B)   // 391

// Scratch: __device__ globals, referenced ONLY from device code.
__device__ float4 g_hw4[(size_t)NN * HH / 4];   // GEMM output (message source)
__device__ float4 g_h4 [(size_t)NN * HH / 4];   // hidden state (layer 1)
__device__ float4 g_h24[(size_t)NN * HH / 4];   // hidden state (layer 2)
__device__ float  g_dinv[NN];                   // rsqrt(deg)
__device__ int    g_deg[NN];
__device__ int    g_off[NN + 1];
__device__ int    g_cur[NN];
__device__ int    g_csr[NE];
__device__ int    g_blocksum[SCAN_NB];
__device__ int    g_is64;

// ---------------------------------------------------------------------------
// Edge dtype detection
// ---------------------------------------------------------------------------
__global__ void k_detect(const int* ei_raw) {
    if (threadIdx.x == 0 && blockIdx.x == 0) {
        int all0 = 1;
        for (int i = 0; i < 64; i++)
            if (ei_raw[2 * i + 1] != 0) { all0 = 0; break; }
        g_is64 = all0;
    }
}

__device__ __forceinline__ int edge_at(const int* ei_raw, size_t idx) {
    return g_is64 ? ei_raw[2 * idx] : ei_raw[idx];
}

// ---------------------------------------------------------------------------
// CSR build + norms
// ---------------------------------------------------------------------------
__global__ void k_zero() {
    int i = blockIdx.x * blockDim.x + threadIdx.x;
    if (i < NN) { g_deg[i] = 0; g_cur[i] = 0; }
}

__global__ void k_deg_count(const int* ei_raw) {
    int e = blockIdx.x * blockDim.x + threadIdx.x;
    if (e >= NE) return;
    int d = edge_at(ei_raw, (size_t)NE + e);
    if (d >= 0 && d < NN) atomicAdd(&g_deg[d], 1);
}

__global__ void k_dinv() {
    int i = blockIdx.x * blockDim.x + threadIdx.x;
    if (i < NN) g_dinv[i] = rsqrtf((float)(g_deg[i] + 1));
}

__global__ void k_scan_reduce() {
    __shared__ int sh[SCAN_B];
    int i = blockIdx.x * SCAN_B + threadIdx.x;
    sh[threadIdx.x] = (i < NN) ? g_deg[i] : 0;
    __syncthreads();
    for (int s = SCAN_B / 2; s > 0; s >>= 1) {
        if (threadIdx.x < s) sh[threadIdx.x] += sh[threadIdx.x + s];
        __syncthreads();
    }
    if (threadIdx.x == 0) g_blocksum[blockIdx.x] = sh[0];
}

__global__ void k_scan_bases() {
    __shared__ int sh[512];
    int i = threadIdx.x;
    int v = (i < SCAN_NB) ? g_blocksum[i] : 0;
    sh[i] = v;
    __syncthreads();
    for (int s = 1; s < 512; s <<= 1) {
        int t = (i >= s) ? sh[i - s] : 0;
        __syncthreads();
        sh[i] += t;
        __syncthreads();
    }
    if (i < SCAN_NB) g_blocksum[i] = sh[i] - v;
    if (i == SCAN_NB - 1) g_off[NN] = sh[i];
}

__global__ void k_scan_offsets() {
    __shared__ int sh[SCAN_B];
    int i = blockIdx.x * SCAN_B + threadIdx.x;
    int v = (i < NN) ? g_deg[i] : 0;
    sh[threadIdx.x] = v;
    __syncthreads();
    for (int s = 1; s < SCAN_B; s <<= 1) {
        int t = (threadIdx.x >= s) ? sh[threadIdx.x - s] : 0;
        __syncthreads();
        sh[threadIdx.x] += t;
        __syncthreads();
    }
    if (i < NN) g_off[i] = g_blocksum[blockIdx.x] + sh[threadIdx.x] - v;
}

__global__ void k_fill(const int* ei_raw) {
    int e = blockIdx.x * blockDim.x + threadIdx.x;
    if (e >= NE) return;
    int s = edge_at(ei_raw, (size_t)e);
    int d = edge_at(ei_raw, (size_t)NE + e);
    if ((unsigned)s >= NN || (unsigned)d >= NN) return;
    int pos = g_off[d] + atomicAdd(&g_cur[d], 1);
    g_csr[pos] = s;
}

// ---------------------------------------------------------------------------
// Split-bf16 tensor GEMM, templated on BN (64 or 128).
// A in smem [m][k2] u32 rows, PAD=20 -> non-trans LDSM (validated).
// B in smem b16 [k][n] rows, pad to BN+8 b16 -> conflict-free uint2 stores
// and conflict-free ldmatrix.x4.trans loads (row stride 16B-group distinct).
// Warps 4m x 2n; warp tile 32 x (BN/2). acc += lo*hi' + hi*lo' + hi*hi'.
// BM=128, BK=32, 256 threads.
// ---------------------------------------------------------------------------
__device__ __forceinline__ void split2(float a, float b, unsigned& hi, unsigned& lo) {
    __nv_bfloat16 ha = __float2bfloat16(a);
    __nv_bfloat16 hb = __float2bfloat16(b);
    __nv_bfloat16 la = __float2bfloat16(a - __bfloat162float(ha));
    __nv_bfloat16 lb = __float2bfloat16(b - __bfloat162float(hb));
    hi = (unsigned)__bfloat16_as_ushort(ha) | ((unsigned)__bfloat16_as_ushort(hb) << 16);
    lo = (unsigned)__bfloat16_as_ushort(la) | ((unsigned)__bfloat16_as_ushort(lb) << 16);
}

__device__ __forceinline__ void ldsm_x4(unsigned& r0, unsigned& r1,
                                        unsigned& r2, unsigned& r3, unsigned addr) {
    asm volatile("ldmatrix.sync.aligned.m8n8.x4.shared.b16 {%0,%1,%2,%3}, [%4];"
                 : "=r"(r0), "=r"(r1), "=r"(r2), "=r"(r3) : "r"(addr));
}
__device__ __forceinline__ void ldsm_x4_t(unsigned& r0, unsigned& r1,
                                          unsigned& r2, unsigned& r3, unsigned addr) {
    asm volatile("ldmatrix.sync.aligned.m8n8.x4.trans.shared.b16 {%0,%1,%2,%3}, [%4];"
                 : "=r"(r0), "=r"(r1), "=r"(r2), "=r"(r3) : "r"(addr));
}

template<int BN, bool RELU_A, int A_SRC, int C_DST>
__global__ void k_mma_gemm(const float* Aext, const float* B, float* Cext,
                           int M, int Kc, int Nc) {
    const float* A = (A_SRC == 1) ? (const float*)g_h4
                   : (A_SRC == 2) ? (const float*)g_h24 : Aext;
    float*       C = (C_DST == 1) ? (float*)g_hw4       : Cext;

    constexpr int BM = 128, BK = 32, PAD = 20;
    constexpr int BPAD = BN + 8;          // b16 per B row (16B-aligned stride)
    constexpr int FN = BN / 16;           // n-frags per warp (4 or 8)
    constexpr int WTN = BN / 2;           // warp tile n

    __shared__ unsigned AsH[BM * PAD], AsL[BM * PAD];
    __shared__ unsigned short BsH[BK * BPAD], BsL[BK * BPAD];

    unsigned aHb = (unsigned)__cvta_generic_to_shared(AsH);
    unsigned aLb = (unsigned)__cvta_generic_to_shared(AsL);
    unsigned bHb = (unsigned)__cvta_generic_to_shared(BsH);
    unsigned bLb = (unsigned)__cvta_generic_to_shared(BsL);

    int tid  = threadIdx.x;
    int wid  = tid >> 5;
    int lane = tid & 31;
    int wm   = wid >> 1;
    int wn   = wid & 1;
    int brow = blockIdx.y * BM;
    int bcol = blockIdx.x * BN;

    float acc[2][FN][4];
    #pragma unroll
    for (int i = 0; i < 2; i++)
        #pragma unroll
        for (int j = 0; j < FN; j++)
            #pragma unroll
            for (int r = 0; r < 4; r++) acc[i][j][r] = 0.0f;

    int mi = lane >> 3;           // ldmatrix quadrant
    int ii = lane & 7;

    for (int k0 = 0; k0 < Kc; k0 += BK) {
        // A tile: 128x32 floats = 1024 float4, 4 per thread; uint2 stores
        #pragma unroll
        for (int l = 0; l < 4; l++) {
            int f  = tid + l * 256;
            int ar = f >> 3;              // 0..127
            int fq = f & 7;               // float4 slot within row
            int gr = brow + ar;
            float4 v = make_float4(0.f, 0.f, 0.f, 0.f);
            if (gr < M) v = *(const float4*)(A + (size_t)gr * Kc + k0 + (fq << 2));
            if (RELU_A) {
                v.x = fmaxf(v.x, 0.f); v.y = fmaxf(v.y, 0.f);
                v.z = fmaxf(v.z, 0.f); v.w = fmaxf(v.w, 0.f);
            }
            unsigned h0, l0, h1, l1;
            split2(v.x, v.y, h0, l0);
            split2(v.z, v.w, h1, l1);
            int k2 = fq << 1;
            *(uint2*)&AsH[ar * PAD + k2] = make_uint2(h0, h1);
            *(uint2*)&AsL[ar * PAD + k2] = make_uint2(l0, l1);
        }
        // B tile: 32 x BN floats; store as b16 [k][n] rows (n-pairs in u32)
        #pragma unroll
        for (int l = 0; l < BN / 64; l++) {
            int r2 = tid >> 4;            // 0..15 -> k rows 2r2, 2r2+1
            int bc = ((tid & 15) << 2) + l * 64;
            float4 v0 = *(const float4*)(B + (size_t)(k0 + 2 * r2    ) * Nc + bcol + bc);
            float4 v1 = *(const float4*)(B + (size_t)(k0 + 2 * r2 + 1) * Nc + bcol + bc);
            unsigned h01, l01, h23, l23;
            split2(v0.x, v0.y, h01, l01);
            split2(v0.z, v0.w, h23, l23);
            *(uint2*)&BsH[(2 * r2) * BPAD + bc] = make_uint2(h01, h23);
            *(uint2*)&BsL[(2 * r2) * BPAD + bc] = make_uint2(l01, l23);
            split2(v1.x, v1.y, h01, l01);
            split2(v1.z, v1.w, h23, l23);
            *(uint2*)&BsH[(2 * r2 + 1) * BPAD + bc] = make_uint2(h01, h23);
            *(uint2*)&BsL[(2 * r2 + 1) * BPAD + bc] = make_uint2(l01, l23);
        }
        __syncthreads();

        #pragma unroll
        for (int sub = 0; sub < 2; sub++) {
            int t0 = sub << 3;            // k2 base within BK (A side)

            unsigned ah[2][4], al[2][4];
            #pragma unroll
            for (int fm = 0; fm < 2; fm++) {
                int row  = wm * 32 + fm * 16 + ((mi & 1) << 3) + ii;
                int colA = t0 + ((mi >> 1) << 2);
                unsigned off = (unsigned)(row * PAD + colA) << 2;
                ldsm_x4(ah[fm][0], ah[fm][1], ah[fm][2], ah[fm][3], aHb + off);
                ldsm_x4(al[fm][0], al[fm][1], al[fm][2], al[fm][3], aLb + off);
            }
            unsigned bh[FN][2], bl[FN][2];
            #pragma unroll
            for (int fp = 0; fp < FN / 2; fp++) {
                int kk = (sub << 4) + ((mi & 1) << 3) + ii;
                int nn = wn * WTN + fp * 16 + ((mi >> 1) << 3);
                unsigned off = (unsigned)(kk * BPAD + nn) << 1;
                ldsm_x4_t(bh[2 * fp][0], bh[2 * fp][1],
                          bh[2 * fp + 1][0], bh[2 * fp + 1][1], bHb + off);
                ldsm_x4_t(bl[2 * fp][0], bl[2 * fp][1],
                          bl[2 * fp + 1][0], bl[2 * fp + 1][1], bLb + off);
            }

            #pragma unroll
            for (int fm = 0; fm < 2; fm++)
                #pragma unroll
                for (int fn = 0; fn < FN; fn++) {
                    float* d = acc[fm][fn];
                    asm volatile(
                        "mma.sync.aligned.m16n8k16.row.col.f32.bf16.bf16.f32 "
                        "{%0,%1,%2,%3}, {%4,%5,%6,%7}, {%8,%9}, {%0,%1,%2,%3};"
                        : "+f"(d[0]), "+f"(d[1]), "+f"(d[2]), "+f"(d[3])
                        : "r"(al[fm][0]), "r"(al[fm][1]), "r"(al[fm][2]), "r"(al[fm][3]),
                          "r"(bh[fn][0]), "r"(bh[fn][1]));
                    asm volatile(
                        "mma.sync.aligned.m16n8k16.row.col.f32.bf16.bf16.f32 "
                        "{%0,%1,%2,%3}, {%4,%5,%6,%7}, {%8,%9}, {%0,%1,%2,%3};"
                        : "+f"(d[0]), "+f"(d[1]), "+f"(d[2]), "+f"(d[3])
                        : "r"(ah[fm][0]), "r"(ah[fm][1]), "r"(ah[fm][2]), "r"(ah[fm][3]),
                          "r"(bl[fn][0]), "r"(bl[fn][1]));
                    asm volatile(
                        "mma.sync.aligned.m16n8k16.row.col.f32.bf16.bf16.f32 "
                        "{%0,%1,%2,%3}, {%4,%5,%6,%7}, {%8,%9}, {%0,%1,%2,%3};"
                        : "+f"(d[0]), "+f"(d[1]), "+f"(d[2]), "+f"(d[3])
                        : "r"(ah[fm][0]), "r"(ah[fm][1]), "r"(ah[fm][2]), "r"(ah[fm][3]),
                          "r"(bh[fn][0]), "r"(bh[fn][1]));
                }
        }
        __syncthreads();
    }

    #pragma unroll
    for (int fm = 0; fm < 2; fm++) {
        int row0 = brow + wm * 32 + fm * 16 + (lane >> 2);
        #pragma unroll
        for (int half = 0; half < 2; half++) {
            int row = row0 + half * 8;
            if (row >= M) continue;
            #pragma unroll
            for (int fn = 0; fn < FN; fn++) {
                int col = bcol + wn * WTN + fn * 8 + 2 * (lane & 3);
                *(float2*)(C + (size_t)row * Nc + col) =
                    make_float2(acc[fm][fn][half * 2 + 0], acc[fm][fn][half * 2 + 1]);
            }
        }
    }
}

// ---------------------------------------------------------------------------
// CSR gather aggregation: warp per node, no atomics.
// ---------------------------------------------------------------------------
template<int DST>
__global__ void k_agg_gather(const float* bias) {
    int gtid = blockIdx.x * blockDim.x + threadIdx.x;
    int node = gtid >> 5;
    int lane = gtid & 31;
    if (node >= NN) return;

    float di = g_dinv[node];
    float ws = di * di;
    const float4* hw = g_hw4 + (size_t)node * (HH / 4);
    float4 b0 = ((const float4*)bias)[lane];
    float4 b1 = ((const float4*)bias)[lane + 32];
    float4 v0 = hw[lane];
    float4 v1 = hw[lane + 32];
    float4 a0 = make_float4(fmaf(ws, v0.x, b0.x), fmaf(ws, v0.y, b0.y),
                            fmaf(ws, v0.z, b0.z), fmaf(ws, v0.w, b0.w));
    float4 a1 = make_float4(fmaf(ws, v1.x, b1.x), fmaf(ws, v1.y, b1.y),
                            fmaf(ws, v1.z, b1.z), fmaf(ws, v1.w, b1.w));

    int e0 = g_off[node], e1 = g_off[node + 1];
    for (int i = e0; i < e1; i++) {
        int s = g_csr[i];
        float w = di * g_dinv[s];
        const float4* hs = g_hw4 + (size_t)s * (HH / 4);
        float4 u0 = hs[lane];
        float4 u1 = hs[lane + 32];
        a0.x = fmaf(w, u0.x, a0.x); a0.y = fmaf(w, u0.y, a0.y);
        a0.z = fmaf(w, u0.z, a0.z); a0.w = fmaf(w, u0.w, a0.w);
        a1.x = fmaf(w, u1.x, a1.x); a1.y = fmaf(w, u1.y, a1.y);
        a1.z = fmaf(w, u1.z, a1.z); a1.w = fmaf(w, u1.w, a1.w);
    }

    float4* out = ((DST == 1) ? g_h4 : g_h24) + (size_t)node * (HH / 4);
    out[lane]      = a0;
    out[lane + 32] = a1;
}

// ---------------------------------------------------------------------------
// Softmax over K=64, warp per row. d_out layout: [S | logits], each NN*KK.
// ---------------------------------------------------------------------------
__global__ void k_softmax(const float* log_tau, float* out) {
    int gtid = blockIdx.x * blockDim.x + threadIdx.x;
    int row  = gtid >> 5;
    int lane = gtid & 31;
    if (row >= NN) return;
    const float* lg = out + (size_t)NN * KK + (size_t)row * KK;
    float inv_tau = __expf(-log_tau[0]);
    float a = lg[lane] * inv_tau;
    float b = lg[lane + 32] * inv_tau;
    float m = fmaxf(a, b);
    #pragma unroll
    for (int off = 16; off > 0; off >>= 1)
        m = fmaxf(m, __shfl_xor_sync(0xFFFFFFFFu, m, off));
    float e0 = __expf(a - m);
    float e1 = __expf(b - m);
    float s = e0 + e1;
    #pragma unroll
    for (int off = 16; off > 0; off >>= 1)
        s += __shfl_xor_sync(0xFFFFFFFFu, s, off);
    float inv = 1.0f / s;
    float* S = out + (size_t)row * KK;
    S[lane]      = e0 * inv;
    S[lane + 32] = e1 * inv;
}

// ---------------------------------------------------------------------------
extern "C" void kernel_launch(void* const* d_in, const int* in_sizes, int n_in,
                              void* d_out, int out_size) {
    const float* x       = (const float*)d_in[0];
    const int*   ei_raw  = (const int*)d_in[1];
    const float* W1      = (const float*)d_in[2];
    const float* b1      = (const float*)d_in[3];
    const float* W2      = (const float*)d_in[4];
    const float* b2      = (const float*)d_in[5];
    const float* Wk      = (const float*)d_in[6];
    const float* log_tau = (const float*)d_in[7];
    float* out = (float*)d_out;

    dim3 grid_H(HH / 128, (NN + 127) / 128);   // BN=128
    dim3 grid_K(KK / 64, (NN + 127) / 128);    // BN=64
    int agg_blocks = (NN * 32 + 255) / 256;

    // Launch order keeps GEMM1 as the 4th launch (ncu capture slot).
    k_detect      <<<1, 32>>>(ei_raw);                         // 1
    k_zero        <<<(NN + 255) / 256, 256>>>();               // 2
    k_deg_count   <<<(NE + 255) / 256, 256>>>(ei_raw);         // 3
    k_mma_gemm<128, false, 0, 1><<<grid_H, 256>>>(x, W1, nullptr, NN, DD, HH);  // 4 <- profiled
    k_dinv        <<<(NN + 255) / 256, 256>>>();               // 5
    k_scan_reduce <<<SCAN_NB, SCAN_B>>>();                     // 6
    k_scan_bases  <<<1, 512>>>();                              // 7
    k_scan_offsets<<<SCAN_NB, SCAN_B>>>();                     // 8
    k_fill        <<<(NE + 255) / 256, 256>>>(ei_raw);         // 9

    // Layer 1 aggregation
    k_agg_gather<1><<<agg_blocks, 256>>>(b1);

    // Layer 2
    k_mma_gemm<128, true, 1, 1><<<grid_H, 256>>>(nullptr, W2, nullptr, NN, HH, HH);
    k_agg_gather<2><<<agg_blocks, 256>>>(b2);

    // Head
    float* logits = out + (size_t)NN * KK;
    k_mma_gemm<64, false, 2, 0><<<grid_K, 256>>>(nullptr, Wk, logits, NN, HH, KK);
    k_softmax<<<(NN + 7) / 8, 256>>>(log_tau, out);
}